// round 7
// baseline (speedup 1.0000x reference)
#include <cuda_runtime.h>
#include <cstdint>

// ---------------- problem constants ----------------
#define B_DIM 128
#define H_DIM 101            // 100 hidden + leading 1
#define AV 10201             // 101*101
#define F_DIM 1030301        // 101^3
#define P_DIM 300
#define NPAD 320             // N padded for 8x40 warp grid
#define KT 16                // K per pipeline tile
#define TILES 64394          // ceil(F_DIM / KT)
#define NCTA 148
#define NTHR 512
#define A_BYTES (128 * KT * 4)        // 8192
#define B_BYTES (NPAD * KT * 4)       // 20480
#define STG_BYTES (A_BYTES + B_BYTES) // 28672
#define NSTAGE 4
#define DYN_SMEM (NSTAGE * STG_BYTES) // 114688

// ---------------- device scratch (no allocs allowed) ----------------
__device__ float g_HA[B_DIM * H_DIM];
__device__ float g_HV[B_DIM * H_DIM];
__device__ float g_HT[B_DIM * H_DIM];
__device__ float g_VT[B_DIM * AV];                 // 5.2 MB, L2-resident
__device__ float g_part[(size_t)NCTA * B_DIM * P_DIM];   // split-K partials
__device__ float g_H[B_DIM * P_DIM];               // relu(fusion@W1^T + b1)

// ---------------- helpers ----------------
__device__ __forceinline__ uint32_t smem_u32(const void* p) {
    uint32_t a;
    asm("{ .reg .u64 t; cvta.to.shared.u64 t, %1; cvt.u32.u64 %0, t; }" : "=r"(a) : "l"(p));
    return a;
}
__device__ __forceinline__ uint32_t f2tf(float x) {   // round-to-nearest tf32
    uint32_t r; asm("cvt.rna.tf32.f32 %0, %1;" : "=r"(r) : "f"(x)); return r;
}
__device__ __forceinline__ void sts128(uint32_t a, uint32_t v0, uint32_t v1,
                                       uint32_t v2, uint32_t v3) {
    asm volatile("st.shared.v4.b32 [%0], {%1,%2,%3,%4};"
                 :: "r"(a), "r"(v0), "r"(v1), "r"(v2), "r"(v3) : "memory");
}
__device__ __forceinline__ void sts32(uint32_t a, uint32_t v) {
    asm volatile("st.shared.b32 [%0], %1;" :: "r"(a), "r"(v) : "memory");
}
__device__ __forceinline__ void lds128(uint32_t a, uint32_t& v0, uint32_t& v1,
                                       uint32_t& v2, uint32_t& v3) {
    asm volatile("ld.shared.v4.b32 {%0,%1,%2,%3}, [%4];"
                 : "=r"(v0), "=r"(v1), "=r"(v2), "=r"(v3) : "r"(a));
}
__device__ __forceinline__ void cpasync4(uint32_t dst, const float* src) {
    asm volatile("cp.async.ca.shared.global [%0], [%1], 4;" :: "r"(dst), "l"(src) : "memory");
}
__device__ __forceinline__ void cp_commit() {
    asm volatile("cp.async.commit_group;" ::: "memory");
}
__device__ __forceinline__ void cp_wait2() {
    asm volatile("cp.async.wait_group 2;" ::: "memory");
}
__device__ __forceinline__ void mma_tf32(float& d0, float& d1, float& d2, float& d3,
                                         uint32_t a0, uint32_t a1, uint32_t a2, uint32_t a3,
                                         uint32_t b0, uint32_t b1) {
    asm volatile("mma.sync.aligned.m16n8k8.row.col.f32.tf32.tf32.f32 "
                 "{%0,%1,%2,%3}, {%4,%5,%6,%7}, {%8,%9}, {%0,%1,%2,%3};"
                 : "+f"(d0), "+f"(d1), "+f"(d2), "+f"(d3)
                 : "r"(a0), "r"(a1), "r"(a2), "r"(a3), "r"(b0), "r"(b1));
}

// ---------------- kernel 1: three small encoders ----------------
__global__ void enc_kernel(const float* __restrict__ ax, const float* __restrict__ vx,
                           const float* __restrict__ tx,
                           const float* __restrict__ Wa, const float* __restrict__ ba,
                           const float* __restrict__ Wv, const float* __restrict__ bv,
                           const float* __restrict__ Wt, const float* __restrict__ bt) {
    __shared__ float xs[300];
    int b = blockIdx.x, m = blockIdx.y;
    const float* x    = (m == 0) ? ax : (m == 1) ? vx : tx;
    const float* W    = (m == 0) ? Wa : (m == 1) ? Wv : Wt;
    const float* bias = (m == 0) ? ba : (m == 1) ? bv : bt;
    float* H          = (m == 0) ? g_HA : (m == 1) ? g_HV : g_HT;
    for (int i = threadIdx.x; i < 300; i += blockDim.x) xs[i] = x[b * 300 + i];
    __syncthreads();
    int j = threadIdx.x;
    if (j == 0) H[b * H_DIM] = 1.0f;
    if (j < 100) {
        const float* w = W + j * 300;
        float s = 0.0f;
        #pragma unroll 4
        for (int p = 0; p < 300; p++) s += xs[p] * __ldg(w + p);
        H[b * H_DIM + 1 + j] = s + __ldg(bias + j);
    }
}

// ---------------- kernel 2: VT[b, v*101+t] = _v[b,v] * _t[b,t] ----------------
__global__ void vt_kernel() {
    __shared__ float hv[H_DIM], ht[H_DIM];
    int b = blockIdx.x;
    if (threadIdx.x < H_DIM) {
        hv[threadIdx.x] = g_HV[b * H_DIM + threadIdx.x];
        ht[threadIdx.x] = g_HT[b * H_DIM + threadIdx.x];
    }
    __syncthreads();
    for (int i = threadIdx.x; i < AV; i += 256) {
        int v = i / 101, t = i - v * 101;
        g_VT[b * AV + i] = hv[v] * ht[t];
    }
}

// ---------------- kernel 3: main split-K mma.sync GEMM ----------------
// SMEM layouts (per stage), k-permuted so each thread's 4 k-values are one float4:
//   A_s[row][c*4 + j] = Afusion[row][k0 + c + 4j], row stride 64B, 128 rows
//   B_s[n]  [c*4 + j] = W1[n][k0 + c + 4j],        row stride 64B, 320 rows (>=300 zero)
__global__ void __launch_bounds__(NTHR, 1) main_kernel(const float* __restrict__ W1) {
    extern __shared__ char dyn[];
    uint32_t base_s = smem_u32(dyn);

    int tid = threadIdx.x, wid = tid >> 5, lane = tid & 31;
    int cta = blockIdx.x;
    int wm = wid & 1;          // M half: rows wm*64
    int wn = wid >> 1;         // N slice: cols wn*40
    int lr = lane >> 2;        // 0..7
    int lc = lane & 3;         // 0..3

    // contiguous K-tile range for this CTA
    int q = TILES / NCTA;                  // 435
    int r = TILES - q * NCTA;              // 14
    int t0 = cta * q + min(cta, r);
    int nt = q + (cta < r ? 1 : 0);

    // ---- producer lambda-ish via macro-free inline ----
    // A tile: thread -> row=tid>>2, c=tid&3, j=0..3 (k = k0 + c + 4j)
    int arow = tid >> 2;
    int acol = tid & 3;
    const float* HAb = g_HA + arow * H_DIM;
    const float* VTb = g_VT + (size_t)arow * AV;
    // B tile: warp handles row-pairs rp = wid + 16*i, i<10; lane<16 -> n=2rp, else n=2rp+1
    int bn = 2 * (wid) + (lane >> 4);      // + 32*i later
    int bk = lane & 15;
    int bc = bk & 3, bj = bk >> 2;

    float acc[4][5][4];
    #pragma unroll
    for (int m = 0; m < 4; m++)
        #pragma unroll
        for (int n = 0; n < 5; n++)
            #pragma unroll
            for (int e = 0; e < 4; e++) acc[m][n][e] = 0.0f;

#define LOAD_STAGE(S, TIDX) do {                                                    \
    uint32_t aB = base_s + (S) * STG_BYTES;                                         \
    uint32_t bB = aB + A_BYTES;                                                     \
    int k0 = (TIDX) * KT;                                                           \
    /* A: fusion on the fly */                                                      \
    {                                                                               \
        uint32_t v[4];                                                              \
        int kb = k0 + acol;                                                         \
        _Pragma("unroll")                                                           \
        for (int j = 0; j < 4; j++) {                                               \
            int k = kb + 4 * j;                                                     \
            float val = 0.0f;                                                       \
            if (k < F_DIM) {                                                        \
                int a = k / AV;                                                     \
                int vt = k - a * AV;                                                \
                val = __ldg(HAb + a) * __ldg(VTb + vt);                             \
            }                                                                       \
            v[j] = f2tf(val);                                                       \
        }                                                                           \
        sts128(aB + arow * 64 + acol * 16, v[0], v[1], v[2], v[3]);                 \
    }                                                                               \
    /* B: W1 rows via cp.async (k-permuted dst) */                                  \
    {                                                                               \
        _Pragma("unroll")                                                           \
        for (int i = 0; i < 10; i++) {                                              \
            int n = bn + 32 * i;                                                    \
            int k = k0 + bk;                                                        \
            uint32_t dst = bB + n * 64 + bc * 16 + bj * 4;                          \
            if (n < 300 && k < F_DIM)                                               \
                cpasync4(dst, W1 + (size_t)n * F_DIM + k);                          \
            else                                                                    \
                sts32(dst, 0u);                                                     \
        }                                                                           \
    }                                                                               \
} while (0)

    // prologue: stages 0..2
    #pragma unroll
    for (int s = 0; s < 3; s++) {
        if (s < nt) LOAD_STAGE(s, t0 + s);
        cp_commit();
    }

    uint32_t aoff = (uint32_t)((wm * 64 + lr) * 64 + lc * 16);          // A frag base (row lr)
    uint32_t boff = (uint32_t)((wn * 40 + lr) * 64 + lc * 16);          // B frag base

    for (int c = 0; c < nt; c++) {
        cp_wait2();
        __syncthreads();
        // issue tile c+3 into stage (c+3)%4 (consumed stage (c-1)%4 is free)
        if (c + 3 < nt) LOAD_STAGE((c + 3) & 3, t0 + c + 3);
        cp_commit();

        uint32_t aB = base_s + (c & 3) * STG_BYTES;
        uint32_t bB = aB + A_BYTES;

        // B fragments: 5 n-tiles x 4 regs (covers both k8 halves), tf32-round
        uint32_t bb[5][4];
        #pragma unroll
        for (int n = 0; n < 5; n++) {
            lds128(bB + boff + n * 8 * 64, bb[n][0], bb[n][1], bb[n][2], bb[n][3]);
            #pragma unroll
            for (int e = 0; e < 4; e++) bb[n][e] = f2tf(__uint_as_float(bb[n][e]));
        }
        // A fragments per m-tile, then 10 MMAs
        #pragma unroll
        for (int m = 0; m < 4; m++) {
            uint32_t ra[4], rb[4];
            lds128(aB + aoff + m * 16 * 64, ra[0], ra[1], ra[2], ra[3]);
            lds128(aB + aoff + (m * 16 + 8) * 64, rb[0], rb[1], rb[2], rb[3]);
            #pragma unroll
            for (int n = 0; n < 5; n++) {
                mma_tf32(acc[m][n][0], acc[m][n][1], acc[m][n][2], acc[m][n][3],
                         ra[0], rb[0], ra[1], rb[1], bb[n][0], bb[n][1]);
                mma_tf32(acc[m][n][0], acc[m][n][1], acc[m][n][2], acc[m][n][3],
                         ra[2], rb[2], ra[3], rb[3], bb[n][2], bb[n][3]);
            }
        }
    }

    // ---- epilogue: deterministic per-CTA partials ----
    float* dst = g_part + (size_t)cta * B_DIM * P_DIM;
    #pragma unroll
    for (int m = 0; m < 4; m++) {
        int row = wm * 64 + m * 16 + lr;
        #pragma unroll
        for (int n = 0; n < 5; n++) {
            int col = wn * 40 + n * 8 + lc * 2;
            if (col < 300) {
                float2 v0 = make_float2(acc[m][n][0], acc[m][n][1]);
                float2 v1 = make_float2(acc[m][n][2], acc[m][n][3]);
                *reinterpret_cast<float2*>(dst + (size_t)row * P_DIM + col) = v0;
                *reinterpret_cast<float2*>(dst + (size_t)(row + 8) * P_DIM + col) = v1;
            }
        }
    }
#undef LOAD_STAGE
}

// ---------------- kernel 4: fixed-order split-K reduce + bias + relu ----------------
__global__ void reduce_kernel(const float* __restrict__ b1) {
    int g = blockIdx.x * blockDim.x + threadIdx.x;
    if (g >= B_DIM * P_DIM) return;
    float s = 0.0f;
    #pragma unroll 4
    for (int c = 0; c < NCTA; c++) s += g_part[(size_t)c * B_DIM * P_DIM + g];
    s += __ldg(b1 + (g % P_DIM));
    g_H[g] = fmaxf(s, 0.0f);
}

// ---------------- kernel 5: output layer ----------------
__global__ void out_kernel(const float* __restrict__ W2, const float* __restrict__ b2,
                           float* __restrict__ out) {
    __shared__ float w[P_DIM];
    int o = blockIdx.x;
    for (int i = threadIdx.x; i < P_DIM; i += blockDim.x) w[i] = W2[o * P_DIM + i];
    __syncthreads();
    int b = threadIdx.x;
    if (b < B_DIM) {
        const float* h = g_H + b * P_DIM;
        float s = __ldg(b2 + o);
        #pragma unroll 4
        for (int p = 0; p < P_DIM; p++) s += h[p] * w[p];
        out[b * P_DIM + o] = fmaxf(s, 0.0f);
    }
}

// ---------------- launch ----------------
extern "C" void kernel_launch(void* const* d_in, const int* in_sizes, int n_in,
                              void* d_out, int out_size) {
    const float* ax = (const float*)d_in[0];
    const float* vx = (const float*)d_in[1];
    const float* tx = (const float*)d_in[2];
    const float* Wa = (const float*)d_in[3];
    const float* ba = (const float*)d_in[4];
    const float* Wv = (const float*)d_in[5];
    const float* bv = (const float*)d_in[6];
    const float* Wt = (const float*)d_in[7];
    const float* bt = (const float*)d_in[8];
    const float* W1 = (const float*)d_in[9];
    const float* b1 = (const float*)d_in[10];
    const float* W2 = (const float*)d_in[11];
    const float* b2 = (const float*)d_in[12];
    float* out = (float*)d_out;

    cudaFuncSetAttribute(main_kernel, cudaFuncAttributeMaxDynamicSharedMemorySize, DYN_SMEM);

    enc_kernel<<<dim3(B_DIM, 3), 128>>>(ax, vx, tx, Wa, ba, Wv, bv, Wt, bt);
    vt_kernel<<<B_DIM, 256>>>();
    main_kernel<<<NCTA, NTHR, DYN_SMEM>>>(W1);
    reduce_kernel<<<(B_DIM * P_DIM + 255) / 256, 256>>>(b1);
    out_kernel<<<P_DIM, 128>>>(W2, b2, out);
}

// round 8
// speedup vs baseline: 1.3802x; 1.3802x over previous
#include <cuda_runtime.h>
#include <cstdint>

// ---------------- problem constants ----------------
#define B_DIM 128
#define H_DIM 101            // 100 hidden + leading 1
#define AV 10201             // 101*101
#define F_DIM 1030301        // 101^3
#define P_DIM 300
#define NPAD 320             // N padded for 4 warps x 80 cols
#define KT 16                // K per pipeline tile
#define TILES 64394          // ceil(F_DIM / KT)
#define NCTA 148
#define NTHR 256
#define A_BYTES (128 * KT * 4)        // 8192
#define B_BYTES (NPAD * KT * 4)       // 20480
#define STG_BYTES (A_BYTES + B_BYTES) // 28672
#define NSTAGE 4
#define DYN_SMEM (NSTAGE * STG_BYTES) // 114688

// ---------------- device scratch (no allocs allowed) ----------------
__device__ float g_HA[B_DIM * H_DIM];
__device__ float g_HV[B_DIM * H_DIM];
__device__ float g_HT[B_DIM * H_DIM];
__device__ float g_VT[B_DIM * AV];                               // 5.2 MB, L2-resident
__device__ __align__(16) float g_part[(size_t)NCTA * B_DIM * P_DIM];  // split-K partials
__device__ __align__(16) float g_H[B_DIM * P_DIM];               // relu(fusion@W1^T + b1)

// ---------------- helpers ----------------
__device__ __forceinline__ uint32_t smem_u32(const void* p) {
    uint32_t a;
    asm("{ .reg .u64 t; cvta.to.shared.u64 t, %1; cvt.u32.u64 %0, t; }" : "=r"(a) : "l"(p));
    return a;
}
__device__ __forceinline__ uint32_t f2tf(float x) {   // round-to-nearest tf32
    uint32_t r; asm("cvt.rna.tf32.f32 %0, %1;" : "=r"(r) : "f"(x)); return r;
}
__device__ __forceinline__ void sts128(uint32_t a, uint32_t v0, uint32_t v1,
                                       uint32_t v2, uint32_t v3) {
    asm volatile("st.shared.v4.b32 [%0], {%1,%2,%3,%4};"
                 :: "r"(a), "r"(v0), "r"(v1), "r"(v2), "r"(v3) : "memory");
}
__device__ __forceinline__ void sts32(uint32_t a, uint32_t v) {
    asm volatile("st.shared.b32 [%0], %1;" :: "r"(a), "r"(v) : "memory");
}
__device__ __forceinline__ void lds128(uint32_t a, uint32_t& v0, uint32_t& v1,
                                       uint32_t& v2, uint32_t& v3) {
    asm volatile("ld.shared.v4.b32 {%0,%1,%2,%3}, [%4];"
                 : "=r"(v0), "=r"(v1), "=r"(v2), "=r"(v3) : "r"(a));
}
__device__ __forceinline__ void cpasync4(uint32_t dst, const float* src) {
    asm volatile("cp.async.ca.shared.global [%0], [%1], 4;" :: "r"(dst), "l"(src) : "memory");
}
__device__ __forceinline__ void cp_commit() {
    asm volatile("cp.async.commit_group;" ::: "memory");
}
__device__ __forceinline__ void cp_wait2() {
    asm volatile("cp.async.wait_group 2;" ::: "memory");
}
__device__ __forceinline__ void mma_tf32(float& d0, float& d1, float& d2, float& d3,
                                         uint32_t a0, uint32_t a1, uint32_t a2, uint32_t a3,
                                         uint32_t b0, uint32_t b1) {
    asm volatile("mma.sync.aligned.m16n8k8.row.col.f32.tf32.tf32.f32 "
                 "{%0,%1,%2,%3}, {%4,%5,%6,%7}, {%8,%9}, {%0,%1,%2,%3};"
                 : "+f"(d0), "+f"(d1), "+f"(d2), "+f"(d3)
                 : "r"(a0), "r"(a1), "r"(a2), "r"(a3), "r"(b0), "r"(b1));
}

// ---------------- kernel 1: three small encoders ----------------
__global__ void enc_kernel(const float* __restrict__ ax, const float* __restrict__ vx,
                           const float* __restrict__ tx,
                           const float* __restrict__ Wa, const float* __restrict__ ba,
                           const float* __restrict__ Wv, const float* __restrict__ bv,
                           const float* __restrict__ Wt, const float* __restrict__ bt) {
    __shared__ float xs[300];
    int b = blockIdx.x, m = blockIdx.y;
    const float* x    = (m == 0) ? ax : (m == 1) ? vx : tx;
    const float* W    = (m == 0) ? Wa : (m == 1) ? Wv : Wt;
    const float* bias = (m == 0) ? ba : (m == 1) ? bv : bt;
    float* H          = (m == 0) ? g_HA : (m == 1) ? g_HV : g_HT;
    for (int i = threadIdx.x; i < 300; i += blockDim.x) xs[i] = x[b * 300 + i];
    __syncthreads();
    int j = threadIdx.x;
    if (j == 0) H[b * H_DIM] = 1.0f;
    if (j < 100) {
        const float* w = W + j * 300;
        float s = 0.0f;
        #pragma unroll 4
        for (int p = 0; p < 300; p++) s += xs[p] * __ldg(w + p);
        H[b * H_DIM + 1 + j] = s + __ldg(bias + j);
    }
}

// ---------------- kernel 2: VT[b, v*101+t] = _v[b,v] * _t[b,t] ----------------
__global__ void vt_kernel() {
    __shared__ float hv[H_DIM], ht[H_DIM];
    int b = blockIdx.x;
    if (threadIdx.x < H_DIM) {
        hv[threadIdx.x] = g_HV[b * H_DIM + threadIdx.x];
        ht[threadIdx.x] = g_HT[b * H_DIM + threadIdx.x];
    }
    __syncthreads();
    for (int i = threadIdx.x; i < AV; i += 256) {
        int v = i / 101, t = i - v * 101;
        g_VT[b * AV + i] = hv[v] * ht[t];
    }
}

// ---------------- kernel 3: main split-K mma.sync GEMM ----------------
// 8 warps, warp grid 2M x 4N: warp covers 64 rows x 80 cols.
// SMEM layouts (per stage), k-permuted: value for k = c + 4j stored at word c*4 + j,
// so a thread's 4 k-values (k = lc, lc+4, lc+8, lc+12) are one contiguous float4.
//   A_s[row][word] : 128 rows x 64 B
//   B_s[n][word]   : 320 rows x 64 B (rows >= 300 zero)
__global__ void __launch_bounds__(NTHR, 1) main_kernel(const float* __restrict__ W1) {
    extern __shared__ char dyn[];
    uint32_t base_s = smem_u32(dyn);

    int tid = threadIdx.x, wid = tid >> 5, lane = tid & 31;
    int cta = blockIdx.x;
    int wm = wid & 1;          // M half: rows wm*64
    int wn = wid >> 1;         // N block: cols wn*80
    int lr = lane >> 2;        // 0..7
    int lc = lane & 3;         // 0..3

    // contiguous K-tile range for this CTA
    int q = TILES / NCTA;                  // 435
    int r = TILES - q * NCTA;              // 14
    int t0 = cta * q + min(cta, r);
    int nt = q + (cta < r ? 1 : 0);

    // A producer mapping: thread -> row = tid>>1, two column-groups c = 2*(tid&1)+{0,1}
    int arow = tid >> 1;
    int ac0  = (tid & 1) * 2;
    const float* HAb = g_HA + arow * H_DIM;
    const float* VTb = g_VT + (size_t)arow * AV;
    // B producer mapping: per i-step, warp covers rows {2*wid, 2*wid+1} + 16*i
    int bn = 2 * wid + (lane >> 4);
    int bk = lane & 15;
    int bc = bk & 3, bj = bk >> 2;

    float acc[4][10][4];
    #pragma unroll
    for (int m = 0; m < 4; m++)
        #pragma unroll
        for (int n = 0; n < 10; n++)
            #pragma unroll
            for (int e = 0; e < 4; e++) acc[m][n][e] = 0.0f;

#define LOAD_STAGE(S, TIDX) do {                                                    \
    uint32_t aB = base_s + (S) * STG_BYTES;                                         \
    uint32_t bB = aB + A_BYTES;                                                     \
    int k0 = (TIDX) * KT;                                                           \
    /* A: fusion on the fly, 2 float4 stores per thread */                          \
    _Pragma("unroll")                                                               \
    for (int cc = 0; cc < 2; cc++) {                                                \
        int c = ac0 + cc;                                                           \
        uint32_t v[4];                                                              \
        _Pragma("unroll")                                                           \
        for (int j = 0; j < 4; j++) {                                               \
            int k = k0 + c + 4 * j;                                                 \
            float val = 0.0f;                                                       \
            if (k < F_DIM) {                                                        \
                int a = k / AV;                                                     \
                int vt = k - a * AV;                                                \
                val = __ldg(HAb + a) * __ldg(VTb + vt);                             \
            }                                                                       \
            v[j] = f2tf(val);                                                       \
        }                                                                           \
        sts128(aB + arow * 64 + c * 16, v[0], v[1], v[2], v[3]);                    \
    }                                                                               \
    /* B: W1 rows via cp.async (k-permuted dst), 20 per thread */                   \
    _Pragma("unroll")                                                               \
    for (int i = 0; i < 20; i++) {                                                  \
        int n = bn + 16 * i;                                                        \
        int k = k0 + bk;                                                            \
        uint32_t dst = bB + n * 64 + bc * 16 + bj * 4;                              \
        if (n < 300 && k < F_DIM)                                                   \
            cpasync4(dst, W1 + (size_t)n * F_DIM + k);                              \
        else                                                                        \
            sts32(dst, 0u);                                                         \
    }                                                                               \
} while (0)

    // prologue: stages 0..2
    #pragma unroll
    for (int s = 0; s < 3; s++) {
        if (s < nt) LOAD_STAGE(s, t0 + s);
        cp_commit();
    }

    uint32_t aoff = (uint32_t)((wm * 64 + lr) * 64 + lc * 16);
    uint32_t boff = (uint32_t)((wn * 80 + lr) * 64 + lc * 16);

    for (int c = 0; c < nt; c++) {
        cp_wait2();
        __syncthreads();
        // issue tile c+3 into stage (c+3)%4 (stage (c-1)%4 fully consumed)
        if (c + 3 < nt) LOAD_STAGE((c + 3) & 3, t0 + c + 3);
        cp_commit();

        uint32_t aB = base_s + (c & 3) * STG_BYTES;
        uint32_t bB = aB + A_BYTES;

        // B fragments: 10 n-tiles x 4 regs (covers both k8 halves)
        uint32_t bb[10][4];
        #pragma unroll
        for (int n = 0; n < 10; n++) {
            lds128(bB + boff + n * 8 * 64, bb[n][0], bb[n][1], bb[n][2], bb[n][3]);
            #pragma unroll
            for (int e = 0; e < 4; e++) bb[n][e] = f2tf(__uint_as_float(bb[n][e]));
        }
        // A fragments per m-tile, then 20 MMAs each
        #pragma unroll
        for (int m = 0; m < 4; m++) {
            uint32_t ra[4], rb[4];
            lds128(aB + aoff + m * 16 * 64, ra[0], ra[1], ra[2], ra[3]);
            lds128(aB + aoff + (m * 16 + 8) * 64, rb[0], rb[1], rb[2], rb[3]);
            #pragma unroll
            for (int n = 0; n < 10; n++) {
                mma_tf32(acc[m][n][0], acc[m][n][1], acc[m][n][2], acc[m][n][3],
                         ra[0], rb[0], ra[1], rb[1], bb[n][0], bb[n][1]);
                mma_tf32(acc[m][n][0], acc[m][n][1], acc[m][n][2], acc[m][n][3],
                         ra[2], rb[2], ra[3], rb[3], bb[n][2], bb[n][3]);
            }
        }
    }

    // ---- epilogue: deterministic per-CTA partials ----
    float* dst = g_part + (size_t)cta * B_DIM * P_DIM;
    #pragma unroll
    for (int m = 0; m < 4; m++) {
        int row = wm * 64 + m * 16 + lr;
        #pragma unroll
        for (int n = 0; n < 10; n++) {
            int col = wn * 80 + n * 8 + lc * 2;
            if (col < 300) {
                float2 v0 = make_float2(acc[m][n][0], acc[m][n][1]);
                float2 v1 = make_float2(acc[m][n][2], acc[m][n][3]);
                *reinterpret_cast<float2*>(dst + (size_t)row * P_DIM + col) = v0;
                *reinterpret_cast<float2*>(dst + (size_t)(row + 8) * P_DIM + col) = v1;
            }
        }
    }
#undef LOAD_STAGE
}

// ---------------- kernel 4: fixed-order split-K reduce + bias + relu ----------------
// float4 lanes + unroll -> MLP ~16, ~22.7 MB read
__global__ void reduce_kernel(const float* __restrict__ b1) {
    int g4 = blockIdx.x * blockDim.x + threadIdx.x;       // float4 index
    const int NG4 = B_DIM * P_DIM / 4;                    // 9600
    if (g4 >= NG4) return;
    const float4* base = reinterpret_cast<const float4*>(g_part);
    float4 s0 = make_float4(0.f, 0.f, 0.f, 0.f);
    float4 s1 = make_float4(0.f, 0.f, 0.f, 0.f);
    #pragma unroll 2
    for (int c = 0; c < NCTA; c += 2) {
        float4 v0 = base[(size_t)c * NG4 + g4];
        float4 v1 = base[(size_t)(c + 1) * NG4 + g4];
        s0.x += v0.x; s0.y += v0.y; s0.z += v0.z; s0.w += v0.w;
        s1.x += v1.x; s1.y += v1.y; s1.z += v1.z; s1.w += v1.w;
    }
    int col = (g4 * 4) % P_DIM;                           // P_DIM % 4 == 0
    float4 o;
    o.x = fmaxf(s0.x + s1.x + __ldg(b1 + col + 0), 0.f);
    o.y = fmaxf(s0.y + s1.y + __ldg(b1 + col + 1), 0.f);
    o.z = fmaxf(s0.z + s1.z + __ldg(b1 + col + 2), 0.f);
    o.w = fmaxf(s0.w + s1.w + __ldg(b1 + col + 3), 0.f);
    reinterpret_cast<float4*>(g_H)[g4] = o;
}

// ---------------- kernel 5: output layer ----------------
__global__ void out_kernel(const float* __restrict__ W2, const float* __restrict__ b2,
                           float* __restrict__ out) {
    __shared__ float w[P_DIM];
    int o = blockIdx.x;
    for (int i = threadIdx.x; i < P_DIM; i += blockDim.x) w[i] = W2[o * P_DIM + i];
    __syncthreads();
    int b = threadIdx.x;
    if (b < B_DIM) {
        const float* h = g_H + b * P_DIM;
        float s = __ldg(b2 + o);
        #pragma unroll 4
        for (int p = 0; p < P_DIM; p++) s += h[p] * w[p];
        out[b * P_DIM + o] = fmaxf(s, 0.0f);
    }
}

// ---------------- launch ----------------
extern "C" void kernel_launch(void* const* d_in, const int* in_sizes, int n_in,
                              void* d_out, int out_size) {
    const float* ax = (const float*)d_in[0];
    const float* vx = (const float*)d_in[1];
    const float* tx = (const float*)d_in[2];
    const float* Wa = (const float*)d_in[3];
    const float* ba = (const float*)d_in[4];
    const float* Wv = (const float*)d_in[5];
    const float* bv = (const float*)d_in[6];
    const float* Wt = (const float*)d_in[7];
    const float* bt = (const float*)d_in[8];
    const float* W1 = (const float*)d_in[9];
    const float* b1 = (const float*)d_in[10];
    const float* W2 = (const float*)d_in[11];
    const float* b2 = (const float*)d_in[12];
    float* out = (float*)d_out;

    cudaFuncSetAttribute(main_kernel, cudaFuncAttributeMaxDynamicSharedMemorySize, DYN_SMEM);

    enc_kernel<<<dim3(B_DIM, 3), 128>>>(ax, vx, tx, Wa, ba, Wv, bv, Wt, bt);
    vt_kernel<<<B_DIM, 256>>>();
    main_kernel<<<NCTA, NTHR, DYN_SMEM>>>(W1);
    reduce_kernel<<<(B_DIM * P_DIM / 4 + 255) / 256, 256>>>(b1);
    out_kernel<<<P_DIM, 128>>>(W2, b2, out);
}

// round 9
// speedup vs baseline: 1.7835x; 1.2922x over previous
#include <cuda_runtime.h>
#include <cstdint>

// ---------------- problem constants ----------------
#define B_DIM 128
#define H_DIM 101            // 100 hidden + leading 1
#define AV 10201             // 101*101
#define F_DIM 1030301        // 101^3
#define P_DIM 300
#define KT 32                // K per pipeline tile
#define TILES 32197          // ceil(F_DIM / 32), last tile has 29 valid k
#define NCTA 148
#define NTHR 256
#define A_BYTES (128 * KT * 4)        // 16384
#define B_BYTES (320 * KT * 4)        // 40960 (rows 300..319 garbage-tolerated)
#define STG_BYTES (A_BYTES + B_BYTES) // 57344
#define DYN_SMEM (3 * STG_BYTES)      // 172032

// ---------------- device scratch (no allocs allowed) ----------------
__device__ float g_HA[B_DIM * H_DIM];
__device__ float g_HV[B_DIM * H_DIM];
__device__ float g_HT[B_DIM * H_DIM];
__device__ float g_VT[B_DIM * AV];                               // 5.2 MB, L2-resident
__device__ __align__(16) float g_part[(size_t)NCTA * B_DIM * P_DIM];  // split-K partials
__device__ __align__(16) float g_R4[4 * B_DIM * P_DIM];          // phase-1 reduction
__device__ __align__(16) float g_H[B_DIM * P_DIM];               // relu(fusion@W1^T + b1)

// ---------------- helpers ----------------
__device__ __forceinline__ uint32_t smem_u32(const void* p) {
    uint32_t a;
    asm("{ .reg .u64 t; cvta.to.shared.u64 t, %1; cvt.u32.u64 %0, t; }" : "=r"(a) : "l"(p));
    return a;
}
__device__ __forceinline__ uint32_t f2tf(float x) {   // round-to-nearest tf32
    uint32_t r; asm("cvt.rna.tf32.f32 %0, %1;" : "=r"(r) : "f"(x)); return r;
}
__device__ __forceinline__ void sts128(uint32_t a, uint32_t v0, uint32_t v1,
                                       uint32_t v2, uint32_t v3) {
    asm volatile("st.shared.v4.b32 [%0], {%1,%2,%3,%4};"
                 :: "r"(a), "r"(v0), "r"(v1), "r"(v2), "r"(v3) : "memory");
}
__device__ __forceinline__ void lds128(uint32_t a, uint32_t& v0, uint32_t& v1,
                                       uint32_t& v2, uint32_t& v3) {
    asm volatile("ld.shared.v4.b32 {%0,%1,%2,%3}, [%4];"
                 : "=r"(v0), "=r"(v1), "=r"(v2), "=r"(v3) : "r"(a));
}
__device__ __forceinline__ void cpasync4(uint32_t dst, const float* src) {
    asm volatile("cp.async.ca.shared.global [%0], [%1], 4;" :: "r"(dst), "l"(src) : "memory");
}
__device__ __forceinline__ void cp_commit() {
    asm volatile("cp.async.commit_group;" ::: "memory");
}
__device__ __forceinline__ void cp_wait1() {
    asm volatile("cp.async.wait_group 1;" ::: "memory");
}
__device__ __forceinline__ void mma_tf32(float& d0, float& d1, float& d2, float& d3,
                                         uint32_t a0, uint32_t a1, uint32_t a2, uint32_t a3,
                                         uint32_t b0, uint32_t b1) {
    asm volatile("mma.sync.aligned.m16n8k8.row.col.f32.tf32.tf32.f32 "
                 "{%0,%1,%2,%3}, {%4,%5,%6,%7}, {%8,%9}, {%0,%1,%2,%3};"
                 : "+f"(d0), "+f"(d1), "+f"(d2), "+f"(d3)
                 : "r"(a0), "r"(a1), "r"(a2), "r"(a3), "r"(b0), "r"(b1));
}

// ---------------- kernel 1: three small encoders ----------------
__global__ void enc_kernel(const float* __restrict__ ax, const float* __restrict__ vx,
                           const float* __restrict__ tx,
                           const float* __restrict__ Wa, const float* __restrict__ ba,
                           const float* __restrict__ Wv, const float* __restrict__ bv,
                           const float* __restrict__ Wt, const float* __restrict__ bt) {
    __shared__ float xs[300];
    int b = blockIdx.x, m = blockIdx.y;
    const float* x    = (m == 0) ? ax : (m == 1) ? vx : tx;
    const float* W    = (m == 0) ? Wa : (m == 1) ? Wv : Wt;
    const float* bias = (m == 0) ? ba : (m == 1) ? bv : bt;
    float* H          = (m == 0) ? g_HA : (m == 1) ? g_HV : g_HT;
    for (int i = threadIdx.x; i < 300; i += blockDim.x) xs[i] = x[b * 300 + i];
    __syncthreads();
    int j = threadIdx.x;
    if (j == 0) H[b * H_DIM] = 1.0f;
    if (j < 100) {
        const float* w = W + j * 300;
        float s = 0.0f;
        #pragma unroll 4
        for (int p = 0; p < 300; p++) s += xs[p] * __ldg(w + p);
        H[b * H_DIM + 1 + j] = s + __ldg(bias + j);
    }
}

// ---------------- kernel 2: VT[b, v*101+t] = _v[b,v] * _t[b,t] ----------------
__global__ void vt_kernel() {
    __shared__ float hv[H_DIM], ht[H_DIM];
    int b = blockIdx.x;
    if (threadIdx.x < H_DIM) {
        hv[threadIdx.x] = g_HV[b * H_DIM + threadIdx.x];
        ht[threadIdx.x] = g_HT[b * H_DIM + threadIdx.x];
    }
    __syncthreads();
    for (int i = threadIdx.x; i < AV; i += 256) {
        int v = i / 101, t = i - v * 101;
        g_VT[b * AV + i] = hv[v] * ht[t];
    }
}

// ---------------- kernel 3: main split-K mma.sync GEMM ----------------
// 8 warps, warp grid 2M x 4N (warp tile 64 x 80). KT=32.
// SMEM per stage: A[128 rows][32 words], B[320 rows][32 words], k contiguous,
// 16B chunks XOR-swizzled: chunk' = chunk ^ ((row & 1) * 4).
// The MMA-slot <-> physical-k bijection is identical for A and B, so contiguous
// storage is legal: a thread's lds128 at chunk (4g+lc) yields phys k 16g+4lc+{0..3},
// consumed as mma1 slots (lc, lc+4) = regs {0,1} and mma2 slots = regs {2,3}.
__global__ void __launch_bounds__(NTHR, 1) main_kernel(const float* __restrict__ W1) {
    extern __shared__ char dyn[];
    uint32_t base_s = smem_u32(dyn);

    int tid = threadIdx.x, wid = tid >> 5, lane = tid & 31;
    int cta = blockIdx.x;
    int wm = wid & 1;          // M half: rows wm*64
    int wn = wid >> 1;         // N block: cols wn*80
    int lr = lane >> 2;        // 0..7
    int lc = lane & 3;         // 0..3
    uint32_t swlo = (uint32_t)(lr & 1) * 4;   // consumer swizzle (row&1 == lr&1 everywhere)

    // contiguous K-tile range for this CTA
    int q = TILES / NCTA;                  // 217
    int r = TILES - q * NCTA;              // 81
    int t0 = cta * q + min(cta, r);
    int nt = q + (cta < r ? 1 : 0);

    // ---- producer state (rolling, advanced once per produced tile) ----
    int kp = t0 * KT;                      // k0 of produce cursor
    int ap = kp / AV;
    int vp = kp - ap * AV;

    // A producer mapping: it in {0,1}: row = it*64 + wid*8 + (lane>>2); chunks (lane&3)+4j
    int prow0 = wid * 8 + (lane >> 2);
    int pc0   = lane & 3;
    // B producer mapping: word idx = tid + 256*i -> n = idx>>5, w = idx&31
    int bn0 = tid >> 5;                    // 0..7
    int bw0 = tid & 31;
    const float* Wrow = W1 + (size_t)bn0 * F_DIM;   // + k later
    uint32_t bdst0 = (uint32_t)(bn0 * 128 + (((bw0 >> 2) ^ ((bn0 & 1) * 4)) * 16) + (bw0 & 3) * 4);

    float acc[4][10][4];
    #pragma unroll
    for (int m = 0; m < 4; m++)
        #pragma unroll
        for (int n = 0; n < 10; n++)
            #pragma unroll
            for (int e = 0; e < 4; e++) acc[m][n][e] = 0.0f;

#define PRODUCE(S) do {                                                               \
    uint32_t aB = base_s + (S) * STG_BYTES;                                           \
    uint32_t bB = aB + A_BYTES;                                                       \
    /* ---- A tile ---- */                                                            \
    if (vp <= AV - KT && kp + KT <= F_DIM) {  /* fast: a constant over tile */        \
        _Pragma("unroll")                                                             \
        for (int it = 0; it < 2; it++) {                                              \
            int row = it * 64 + prow0;                                                \
            float ha = g_HA[row * H_DIM + ap];                                        \
            const float* vrow = g_VT + (size_t)row * AV + vp;                         \
            uint32_t abase = aB + row * 128;                                          \
            uint32_t rsw = (uint32_t)(row & 1) * 4;                                   \
            _Pragma("unroll")                                                         \
            for (int j = 0; j < 2; j++) {                                             \
                int c = pc0 + 4 * j;                                                  \
                uint32_t v0 = f2tf(ha * vrow[4 * c + 0]);                             \
                uint32_t v1 = f2tf(ha * vrow[4 * c + 1]);                             \
                uint32_t v2 = f2tf(ha * vrow[4 * c + 2]);                             \
                uint32_t v3 = f2tf(ha * vrow[4 * c + 3]);                             \
                sts128(abase + (((uint32_t)c ^ rsw) * 16), v0, v1, v2, v3);           \
            }                                                                         \
        }                                                                             \
    } else {                                  /* slow: per-element */                 \
        _Pragma("unroll")                                                             \
        for (int it = 0; it < 2; it++) {                                              \
            int row = it * 64 + prow0;                                                \
            uint32_t abase = aB + row * 128;                                          \
            uint32_t rsw = (uint32_t)(row & 1) * 4;                                   \
            _Pragma("unroll")                                                         \
            for (int j = 0; j < 2; j++) {                                             \
                int c = pc0 + 4 * j;                                                  \
                uint32_t v[4];                                                        \
                _Pragma("unroll")                                                     \
                for (int e = 0; e < 4; e++) {                                         \
                    int k = kp + 4 * c + e;                                           \
                    float val = 0.0f;                                                 \
                    if (k < F_DIM) {                                                  \
                        int a = (int)((unsigned)k / AV);                              \
                        int vt = k - a * AV;                                          \
                        val = g_HA[row * H_DIM + a] * g_VT[(size_t)row * AV + vt];    \
                    }                                                                 \
                    v[e] = f2tf(val);                                                 \
                }                                                                     \
                sts128(abase + (((uint32_t)c ^ rsw) * 16), v[0], v[1], v[2], v[3]);   \
            }                                                                         \
        }                                                                             \
    }                                                                                 \
    /* ---- B tile: 300 rows x 32 words, rolling pointers ---- */                     \
    {                                                                                 \
        int kk = kp + bw0;                                                            \
        const float* src = Wrow + ((kk < F_DIM) ? kk : 0);  /* clamp: A zeros cover */\
        uint32_t dst = bB + bdst0;                                                    \
        _Pragma("unroll")                                                             \
        for (int i = 0; i < 37; i++) {                                                \
            cpasync4(dst, src);                                                       \
            dst += 8 * 128;                                                           \
            src += (size_t)8 * F_DIM;                                                 \
        }                                                                             \
        if (tid < 128) cpasync4(dst, src);  /* rows 296..299 */                       \
    }                                                                                 \
    /* advance rolling k state */                                                     \
    kp += KT; vp += KT; if (vp >= AV) { vp -= AV; ap++; }                             \
} while (0)

    // prologue: produce stages 0,1
    PRODUCE(0); cp_commit();
    PRODUCE(1); cp_commit();

    uint32_t aoff = (uint32_t)((wm * 64 + lr) * 128);
    uint32_t boff = (uint32_t)((wn * 80 + lr) * 128);

    int stage_c = 0, stage_p = 2;
    for (int c = 0; c < nt; c++) {
        cp_wait1();
        __syncthreads();
        if (c + 2 < nt) PRODUCE(stage_p);
        cp_commit();

        uint32_t aB = base_s + stage_c * STG_BYTES;
        uint32_t bB = aB + A_BYTES;

        #pragma unroll
        for (int g = 0; g < 2; g++) {
            uint32_t chc = (((uint32_t)(4 * g + lc)) ^ swlo) * 16;
            // B fragments: 10 n-tiles x 4 regs
            uint32_t bb[10][4];
            uint32_t baddr = bB + boff + chc;
            #pragma unroll
            for (int n = 0; n < 10; n++) {
                lds128(baddr, bb[n][0], bb[n][1], bb[n][2], bb[n][3]);
                baddr += 8 * 128;
            }
            #pragma unroll
            for (int n = 0; n < 10; n++)
                #pragma unroll
                for (int e = 0; e < 4; e++) bb[n][e] = f2tf(__uint_as_float(bb[n][e]));
            // A fragments + MMAs
            uint32_t aaddr = aB + aoff + chc;
            #pragma unroll
            for (int m = 0; m < 4; m++) {
                uint32_t ra[4], rb[4];
                lds128(aaddr, ra[0], ra[1], ra[2], ra[3]);
                lds128(aaddr + 8 * 128, rb[0], rb[1], rb[2], rb[3]);
                aaddr += 16 * 128;
                #pragma unroll
                for (int n = 0; n < 10; n++) {
                    mma_tf32(acc[m][n][0], acc[m][n][1], acc[m][n][2], acc[m][n][3],
                             ra[0], rb[0], ra[1], rb[1], bb[n][0], bb[n][1]);
                    mma_tf32(acc[m][n][0], acc[m][n][1], acc[m][n][2], acc[m][n][3],
                             ra[2], rb[2], ra[3], rb[3], bb[n][2], bb[n][3]);
                }
            }
        }
        stage_c = (stage_c == 2) ? 0 : stage_c + 1;
        stage_p = (stage_p == 2) ? 0 : stage_p + 1;
    }

    // ---- epilogue: deterministic per-CTA partials ----
    float* dst = g_part + (size_t)cta * B_DIM * P_DIM;
    #pragma unroll
    for (int m = 0; m < 4; m++) {
        int row = wm * 64 + m * 16 + lr;
        #pragma unroll
        for (int n = 0; n < 10; n++) {
            int col = wn * 80 + n * 8 + lc * 2;
            if (col < 300) {
                float2 v0 = make_float2(acc[m][n][0], acc[m][n][1]);
                float2 v1 = make_float2(acc[m][n][2], acc[m][n][3]);
                *reinterpret_cast<float2*>(dst + (size_t)row * P_DIM + col) = v0;
                *reinterpret_cast<float2*>(dst + (size_t)(row + 8) * P_DIM + col) = v1;
            }
        }
    }
#undef PRODUCE
}

// ---------------- kernel 4a: split-K reduce phase 1 (148 -> 4) ----------------
__global__ void reduce1_kernel() {
    const int NG4 = B_DIM * P_DIM / 4;                    // 9600
    int g4 = blockIdx.x * blockDim.x + threadIdx.x;
    if (g4 >= NG4) return;
    int part = blockIdx.y;                                // 0..3, 37 CTAs each
    const float4* base = reinterpret_cast<const float4*>(g_part) + (size_t)part * 37 * NG4 + g4;
    float4 s0 = make_float4(0.f, 0.f, 0.f, 0.f);
    float4 s1 = make_float4(0.f, 0.f, 0.f, 0.f);
    #pragma unroll 4
    for (int c = 0; c < 36; c += 2) {
        float4 v0 = base[(size_t)c * NG4];
        float4 v1 = base[(size_t)(c + 1) * NG4];
        s0.x += v0.x; s0.y += v0.y; s0.z += v0.z; s0.w += v0.w;
        s1.x += v1.x; s1.y += v1.y; s1.z += v1.z; s1.w += v1.w;
    }
    float4 v = base[(size_t)36 * NG4];
    float4 o;
    o.x = s0.x + s1.x + v.x; o.y = s0.y + s1.y + v.y;
    o.z = s0.z + s1.z + v.z; o.w = s0.w + s1.w + v.w;
    reinterpret_cast<float4*>(g_R4)[part * NG4 + g4] = o;
}

// ---------------- kernel 4b: reduce phase 2 + bias + relu ----------------
__global__ void reduce2_kernel(const float* __restrict__ b1) {
    const int NG4 = B_DIM * P_DIM / 4;
    int g4 = blockIdx.x * blockDim.x + threadIdx.x;
    if (g4 >= NG4) return;
    const float4* R = reinterpret_cast<const float4*>(g_R4);
    float4 a = R[0 * NG4 + g4], b = R[1 * NG4 + g4];
    float4 c = R[2 * NG4 + g4], d = R[3 * NG4 + g4];
    int col = (g4 * 4) % P_DIM;
    float4 o;
    o.x = fmaxf(a.x + b.x + c.x + d.x + __ldg(b1 + col + 0), 0.f);
    o.y = fmaxf(a.y + b.y + c.y + d.y + __ldg(b1 + col + 1), 0.f);
    o.z = fmaxf(a.z + b.z + c.z + d.z + __ldg(b1 + col + 2), 0.f);
    o.w = fmaxf(a.w + b.w + c.w + d.w + __ldg(b1 + col + 3), 0.f);
    reinterpret_cast<float4*>(g_H)[g4] = o;
}

// ---------------- kernel 5: output layer ----------------
__global__ void out_kernel(const float* __restrict__ W2, const float* __restrict__ b2,
                           float* __restrict__ out) {
    __shared__ float w[P_DIM];
    int o = blockIdx.x;
    for (int i = threadIdx.x; i < P_DIM; i += blockDim.x) w[i] = W2[o * P_DIM + i];
    __syncthreads();
    int b = threadIdx.x;
    if (b < B_DIM) {
        const float* h = g_H + b * P_DIM;
        float s = __ldg(b2 + o);
        #pragma unroll 4
        for (int p = 0; p < P_DIM; p++) s += h[p] * w[p];
        out[b * P_DIM + o] = fmaxf(s, 0.0f);
    }
}

// ---------------- launch ----------------
extern "C" void kernel_launch(void* const* d_in, const int* in_sizes, int n_in,
                              void* d_out, int out_size) {
    const float* ax = (const float*)d_in[0];
    const float* vx = (const float*)d_in[1];
    const float* tx = (const float*)d_in[2];
    const float* Wa = (const float*)d_in[3];
    const float* ba = (const float*)d_in[4];
    const float* Wv = (const float*)d_in[5];
    const float* bv = (const float*)d_in[6];
    const float* Wt = (const float*)d_in[7];
    const float* bt = (const float*)d_in[8];
    const float* W1 = (const float*)d_in[9];
    const float* b1 = (const float*)d_in[10];
    const float* W2 = (const float*)d_in[11];
    const float* b2 = (const float*)d_in[12];
    float* out = (float*)d_out;

    cudaFuncSetAttribute(main_kernel, cudaFuncAttributeMaxDynamicSharedMemorySize, DYN_SMEM);

    enc_kernel<<<dim3(B_DIM, 3), 128>>>(ax, vx, tx, Wa, ba, Wv, bv, Wt, bt);
    vt_kernel<<<B_DIM, 256>>>();
    main_kernel<<<NCTA, NTHR, DYN_SMEM>>>(W1);
    reduce1_kernel<<<dim3((B_DIM * P_DIM / 4 + 255) / 256, 4), 256>>>();
    reduce2_kernel<<<(B_DIM * P_DIM / 4 + 255) / 256, 256>>>(b1);
    out_kernel<<<P_DIM, 128>>>(W2, b2, out);
}